// round 10
// baseline (speedup 1.0000x reference)
#include <cuda_runtime.h>
#include <cuda_bf16.h>

// GCN 2-layer, minimal-traffic formulation:
//   y[i]   = x[i] * dinv[i]  (5 floats padded to 8 = one 32B L2 sector)
//   z[d]   = sum_edges y[src]          (red.v4 + red.f32)
//   zt     = z*dinv + x*dinv^2 ; h = relu(zt@W1+b1) ; s = h.W2
//   t[i]   = s[i]*dinv[i]
//   acc[d] = sum_edges t[src]          (1 atomic/edge)
//   out[i] = acc[i]*dinv[i] + s[i]*dinv[i]^2 + b2
//
// k_node reads weights straight from the input pointers: all accesses are
// warp-uniform -> one L1-broadcast request per load, 2.6KB working set stays
// L1-resident. No constant bank, no copy nodes.

#define MAXN 131072
#define IN_DIM 5
#define PAD 8
#define HID 128

__device__ float g_deg[MAXN];
__device__ float g_dinv[MAXN];
__device__ __align__(128) float g_y[MAXN * PAD];
__device__ __align__(128) float g_z[MAXN * PAD];
__device__ float g_t[MAXN];
__device__ float g_acc[MAXN];

__device__ __forceinline__ void red_v4(float* p, float a, float b, float c, float d) {
    asm volatile("red.global.add.v4.f32 [%0], {%1, %2, %3, %4};"
                 :: "l"(p), "f"(a), "f"(b), "f"(c), "f"(d) : "memory");
}

__device__ __forceinline__ unsigned long long fma2(unsigned long long a,
                                                   unsigned long long b,
                                                   unsigned long long c) {
    unsigned long long d;
    asm("fma.rn.f32x2 %0, %1, %2, %3;" : "=l"(d) : "l"(a), "l"(b), "l"(c));
    return d;
}
__device__ __forceinline__ unsigned long long pack2(float lo, float hi) {
    unsigned long long d;
    asm("mov.b64 %0, {%1, %2};" : "=l"(d) : "f"(lo), "f"(hi));
    return d;
}
__device__ __forceinline__ void unpack2(unsigned long long v, float& lo, float& hi) {
    asm("mov.b64 {%0, %1}, %2;" : "=f"(lo), "=f"(hi) : "l"(v));
}
__device__ __forceinline__ unsigned long long ldg2(const float* p) {
    unsigned long long v;
    asm("ld.global.nc.b64 %0, [%1];" : "=l"(v) : "l"(p));
    return v;
}

__global__ void k_zero(int n) {
    int i = blockIdx.x * blockDim.x + threadIdx.x;
    if (i >= n) return;
    g_deg[i] = 0.0f;
    g_acc[i] = 0.0f;
    float4 z4 = make_float4(0.f, 0.f, 0.f, 0.f);
    *(float4*)&g_z[i * PAD] = z4;
    *(float4*)&g_z[i * PAD + 4] = z4;
}

// ---- degree: 1 edge/thread (measured-fastest config) ----
__global__ void k_degree(const int* __restrict__ dst, int E) {
    int e = blockIdx.x * blockDim.x + threadIdx.x;
    if (e >= E) return;
    atomicAdd(&g_deg[dst[e]], 1.0f);
}

// ---- dinv + scaled padded features ----
__global__ void k_prep(const float* __restrict__ x, int n) {
    int i = blockIdx.x * blockDim.x + threadIdx.x;
    if (i >= n) return;
    float di = rsqrtf(g_deg[i] + 1.0f);
    g_dinv[i] = di;
    float y0 = x[i * IN_DIM + 0] * di;
    float y1 = x[i * IN_DIM + 1] * di;
    float y2 = x[i * IN_DIM + 2] * di;
    float y3 = x[i * IN_DIM + 3] * di;
    float y4 = x[i * IN_DIM + 4] * di;
    *(float4*)&g_y[i * PAD] = make_float4(y0, y1, y2, y3);
    *(float4*)&g_y[i * PAD + 4] = make_float4(y4, 0.f, 0.f, 0.f);
}

// ---- edge pass 1: z[dst] += y[src], 1 edge/thread ----
__global__ void k_edge_agg1(const int* __restrict__ src, const int* __restrict__ dst, int E) {
    int e = blockIdx.x * blockDim.x + threadIdx.x;
    if (e >= E) return;
    int s = src[e];
    int d = dst[e];
    float4 a = *(const float4*)&g_y[s * PAD];
    float h = g_y[s * PAD + 4];
    red_v4(&g_z[d * PAD], a.x, a.y, a.z, a.w);
    atomicAdd(&g_z[d * PAD + 4], h);
}

// ---- per-node MLP: 1 thread/node, f32x2 packed FMA, uniform-LDG weights ----
__global__ void k_node(const float* __restrict__ x,
                       const float* __restrict__ W1, const float* __restrict__ b1,
                       const float* __restrict__ W2, const float* __restrict__ b2,
                       float* __restrict__ out, int n) {
    int i = blockIdx.x * blockDim.x + threadIdx.x;
    if (i >= n) return;

    float di = g_dinv[i];
    float d2 = di * di;
    float4 z4 = *(const float4*)&g_z[i * PAD];
    float z5  = g_z[i * PAD + 4];
    float zt0 = z4.x * di + x[i * IN_DIM + 0] * d2;
    float zt1 = z4.y * di + x[i * IN_DIM + 1] * d2;
    float zt2 = z4.z * di + x[i * IN_DIM + 2] * d2;
    float zt3 = z4.w * di + x[i * IN_DIM + 3] * d2;
    float zt4 = z5  * di + x[i * IN_DIM + 4] * d2;

    unsigned long long zp0 = pack2(zt0, zt0);
    unsigned long long zp1 = pack2(zt1, zt1);
    unsigned long long zp2 = pack2(zt2, zt2);
    unsigned long long zp3 = pack2(zt3, zt3);
    unsigned long long zp4 = pack2(zt4, zt4);

    float s0 = 0.0f, s1 = 0.0f, s2 = 0.0f, s3 = 0.0f;
#pragma unroll
    for (int k = 0; k < HID; k += 4) {
        // pair A: units k, k+1
        unsigned long long a = ldg2(&b1[k]);
        a = fma2(zp0, ldg2(&W1[0 * HID + k]), a);
        a = fma2(zp1, ldg2(&W1[1 * HID + k]), a);
        a = fma2(zp2, ldg2(&W1[2 * HID + k]), a);
        a = fma2(zp3, ldg2(&W1[3 * HID + k]), a);
        a = fma2(zp4, ldg2(&W1[4 * HID + k]), a);
        // pair B: units k+2, k+3
        unsigned long long b = ldg2(&b1[k + 2]);
        b = fma2(zp0, ldg2(&W1[0 * HID + k + 2]), b);
        b = fma2(zp1, ldg2(&W1[1 * HID + k + 2]), b);
        b = fma2(zp2, ldg2(&W1[2 * HID + k + 2]), b);
        b = fma2(zp3, ldg2(&W1[3 * HID + k + 2]), b);
        b = fma2(zp4, ldg2(&W1[4 * HID + k + 2]), b);
        float a0, a1, b0, b1v;
        unpack2(a, a0, a1);
        unpack2(b, b0, b1v);
        float w2a0, w2a1, w2b0, w2b1;
        unpack2(ldg2(&W2[k]), w2a0, w2a1);
        unpack2(ldg2(&W2[k + 2]), w2b0, w2b1);
        s0 = fmaf(fmaxf(a0, 0.0f), w2a0, s0);
        s1 = fmaf(fmaxf(a1, 0.0f), w2a1, s1);
        s2 = fmaf(fmaxf(b0, 0.0f), w2b0, s2);
        s3 = fmaf(fmaxf(b1v, 0.0f), w2b1, s3);
    }
    float s = (s0 + s1) + (s2 + s3);
    g_t[i] = s * di;
    out[i] = s * d2 + __ldg(&b2[0]);
}

// ---- edge pass 2: acc[dst] += t[src], 1 edge/thread ----
__global__ void k_edge_agg2(const int* __restrict__ src, const int* __restrict__ dst, int E) {
    int e = blockIdx.x * blockDim.x + threadIdx.x;
    if (e >= E) return;
    atomicAdd(&g_acc[dst[e]], g_t[src[e]]);
}

__global__ void k_final(float* __restrict__ out, int n) {
    int i = blockIdx.x * blockDim.x + threadIdx.x;
    if (i >= n) return;
    out[i] += g_acc[i] * g_dinv[i];
}

extern "C" void kernel_launch(void* const* d_in, const int* in_sizes, int n_in,
                              void* d_out, int out_size) {
    const float* x  = (const float*)d_in[0];
    const int* ei   = (const int*)d_in[1];   // [2, E]: src row then dst row
    const float* W1 = (const float*)d_in[2];
    const float* b1 = (const float*)d_in[3];
    const float* W2 = (const float*)d_in[4];
    const float* b2 = (const float*)d_in[5];
    float* out = (float*)d_out;

    int n = in_sizes[0] / IN_DIM;
    int E = in_sizes[1] / 2;
    const int* src = ei;
    const int* dst = ei + E;

    const int TB = 256;
    int gb_n = (n + TB - 1) / TB;
    int gb_e = (E + TB - 1) / TB;

    k_zero<<<gb_n, TB>>>(n);
    k_degree<<<gb_e, TB>>>(dst, E);
    k_prep<<<gb_n, TB>>>(x, n);
    k_edge_agg1<<<gb_e, TB>>>(src, dst, E);
    k_node<<<gb_n, TB>>>(x, W1, b1, W2, b2, out, n);
    k_edge_agg2<<<gb_e, TB>>>(src, dst, E);
    k_final<<<gb_n, TB>>>(out, n);
}

// round 11
// speedup vs baseline: 1.1003x; 1.1003x over previous
#include <cuda_runtime.h>
#include <cuda_bf16.h>

// GCN 2-layer, minimal-traffic formulation:
//   y[i]   = x[i] * dinv[i]  (5 floats padded to 8 = one 32B L2 sector)
//   z[d]   = sum_edges y[src]          (red.v4 + red.f32)
//   zt     = z*dinv + x*dinv^2 ; h = relu(zt@W1+b1) ; s = h.W2 ; t = s*dinv
//   out[d] = dinv[d]*(sum_edges t[src] + t[d]) + b2

#define MAXN 131072
#define IN_DIM 5
#define PAD 8
#define HID 128

__device__ float g_deg[MAXN];
__device__ float g_dinv[MAXN];
__device__ __align__(128) float g_y[MAXN * PAD];
__device__ __align__(128) float g_z[MAXN * PAD];
__device__ float g_t[MAXN];

__device__ __forceinline__ void red_v4(float* p, float a, float b, float c, float d) {
    asm volatile("red.global.add.v4.f32 [%0], {%1, %2, %3, %4};"
                 :: "l"(p), "f"(a), "f"(b), "f"(c), "f"(d) : "memory");
}

__device__ __forceinline__ unsigned long long fma2(unsigned long long a,
                                                   unsigned long long b,
                                                   unsigned long long c) {
    unsigned long long d;
    asm("fma.rn.f32x2 %0, %1, %2, %3;" : "=l"(d) : "l"(a), "l"(b), "l"(c));
    return d;
}
__device__ __forceinline__ unsigned long long pack2(float lo, float hi) {
    unsigned long long d;
    asm("mov.b64 %0, {%1, %2};" : "=l"(d) : "f"(lo), "f"(hi));
    return d;
}
__device__ __forceinline__ void unpack2(unsigned long long v, float& lo, float& hi) {
    asm("mov.b64 {%0, %1}, %2;" : "=f"(lo), "=f"(hi) : "l"(v));
}

__global__ void k_zero(int n) {
    int i = blockIdx.x * blockDim.x + threadIdx.x;
    if (i >= n) return;
    g_deg[i] = 0.0f;
    float4 z4 = make_float4(0.f, 0.f, 0.f, 0.f);
    *(float4*)&g_z[i * PAD] = z4;
    *(float4*)&g_z[i * PAD + 4] = z4;
}

// ---- degree: 1 edge/thread (measured-fastest config) ----
__global__ void k_degree(const int* __restrict__ dst, int E) {
    int e = blockIdx.x * blockDim.x + threadIdx.x;
    if (e >= E) return;
    atomicAdd(&g_deg[dst[e]], 1.0f);
}

// ---- dinv + scaled padded features ----
__global__ void k_prep(const float* __restrict__ x, int n) {
    int i = blockIdx.x * blockDim.x + threadIdx.x;
    if (i >= n) return;
    float di = rsqrtf(g_deg[i] + 1.0f);
    g_dinv[i] = di;
    float y0 = x[i * IN_DIM + 0] * di;
    float y1 = x[i * IN_DIM + 1] * di;
    float y2 = x[i * IN_DIM + 2] * di;
    float y3 = x[i * IN_DIM + 3] * di;
    float y4 = x[i * IN_DIM + 4] * di;
    *(float4*)&g_y[i * PAD] = make_float4(y0, y1, y2, y3);
    *(float4*)&g_y[i * PAD + 4] = make_float4(y4, 0.f, 0.f, 0.f);
}

// ---- edge pass 1: z[dst] += y[src], 1 edge/thread ----
__global__ void k_edge_agg1(const int* __restrict__ src, const int* __restrict__ dst, int E) {
    int e = blockIdx.x * blockDim.x + threadIdx.x;
    if (e >= E) return;
    int s = src[e];
    int d = dst[e];
    float4 a = *(const float4*)&g_y[s * PAD];
    float h = g_y[s * PAD + 4];
    red_v4(&g_z[d * PAD], a.x, a.y, a.z, a.w);
    atomicAdd(&g_z[d * PAD + 4], h);
}

// ---- per-node MLP: 1 thread/node, smem weights, f32x2 pair math ----
// sW1 is the raw row-major W1 so pairs (k,k+1) are contiguous -> LDS.64,
// broadcast across the warp (uniform index). Two independent f32x2 chains.
__global__ void k_node(const float* __restrict__ x,
                       const float* __restrict__ W1, const float* __restrict__ b1,
                       const float* __restrict__ W2, const float* __restrict__ b2,
                       float* __restrict__ out, int n) {
    __shared__ __align__(16) float sW1[IN_DIM * HID];
    __shared__ __align__(16) float sb1[HID];
    __shared__ __align__(16) float sW2[HID];
    for (int i = threadIdx.x; i < IN_DIM * HID; i += blockDim.x) sW1[i] = W1[i];
    if (threadIdx.x < HID) {
        sb1[threadIdx.x] = b1[threadIdx.x];
        sW2[threadIdx.x] = W2[threadIdx.x];
    }
    __syncthreads();

    int i = blockIdx.x * blockDim.x + threadIdx.x;
    if (i >= n) return;

    float di = g_dinv[i];
    float d2 = di * di;
    float4 z4 = *(const float4*)&g_z[i * PAD];
    float z5  = g_z[i * PAD + 4];
    float zt0 = z4.x * di + x[i * IN_DIM + 0] * d2;
    float zt1 = z4.y * di + x[i * IN_DIM + 1] * d2;
    float zt2 = z4.z * di + x[i * IN_DIM + 2] * d2;
    float zt3 = z4.w * di + x[i * IN_DIM + 3] * d2;
    float zt4 = z5  * di + x[i * IN_DIM + 4] * d2;

    unsigned long long zp0 = pack2(zt0, zt0);
    unsigned long long zp1 = pack2(zt1, zt1);
    unsigned long long zp2 = pack2(zt2, zt2);
    unsigned long long zp3 = pack2(zt3, zt3);
    unsigned long long zp4 = pack2(zt4, zt4);

    float s0 = 0.0f, s1 = 0.0f, s2 = 0.0f, s3 = 0.0f;
#pragma unroll
    for (int k = 0; k < HID; k += 4) {
        // chain A: units k, k+1
        unsigned long long a = *(const unsigned long long*)&sb1[k];
        a = fma2(zp0, *(const unsigned long long*)&sW1[0 * HID + k], a);
        a = fma2(zp1, *(const unsigned long long*)&sW1[1 * HID + k], a);
        a = fma2(zp2, *(const unsigned long long*)&sW1[2 * HID + k], a);
        a = fma2(zp3, *(const unsigned long long*)&sW1[3 * HID + k], a);
        a = fma2(zp4, *(const unsigned long long*)&sW1[4 * HID + k], a);
        // chain B: units k+2, k+3
        unsigned long long b = *(const unsigned long long*)&sb1[k + 2];
        b = fma2(zp0, *(const unsigned long long*)&sW1[0 * HID + k + 2], b);
        b = fma2(zp1, *(const unsigned long long*)&sW1[1 * HID + k + 2], b);
        b = fma2(zp2, *(const unsigned long long*)&sW1[2 * HID + k + 2], b);
        b = fma2(zp3, *(const unsigned long long*)&sW1[3 * HID + k + 2], b);
        b = fma2(zp4, *(const unsigned long long*)&sW1[4 * HID + k + 2], b);
        float a0, a1, b0, b1v;
        unpack2(a, a0, a1);
        unpack2(b, b0, b1v);
        float w2a0, w2a1, w2b0, w2b1;
        unpack2(*(const unsigned long long*)&sW2[k], w2a0, w2a1);
        unpack2(*(const unsigned long long*)&sW2[k + 2], w2b0, w2b1);
        s0 = fmaf(fmaxf(a0, 0.0f), w2a0, s0);
        s1 = fmaf(fmaxf(a1, 0.0f), w2a1, s1);
        s2 = fmaf(fmaxf(b0, 0.0f), w2b0, s2);
        s3 = fmaf(fmaxf(b1v, 0.0f), w2b1, s3);
    }
    float s = (s0 + s1) + (s2 + s3);
    float t = s * di;
    g_t[i] = t;
    out[i] = t;              // self-loop term, pre-scale; final pass applies *dinv + b2
}

// ---- edge pass 2: out[dst] += t[src] (reads only g_t -> no race) ----
__global__ void k_edge_agg2(const int* __restrict__ src, const int* __restrict__ dst,
                            float* __restrict__ out, int E) {
    int e = blockIdx.x * blockDim.x + threadIdx.x;
    if (e >= E) return;
    atomicAdd(&out[dst[e]], g_t[src[e]]);
}

__global__ void k_final(float* __restrict__ out, const float* __restrict__ b2, int n) {
    int i = blockIdx.x * blockDim.x + threadIdx.x;
    if (i >= n) return;
    out[i] = out[i] * g_dinv[i] + __ldg(&b2[0]);
}

extern "C" void kernel_launch(void* const* d_in, const int* in_sizes, int n_in,
                              void* d_out, int out_size) {
    const float* x  = (const float*)d_in[0];
    const int* ei   = (const int*)d_in[1];   // [2, E]: src row then dst row
    const float* W1 = (const float*)d_in[2];
    const float* b1 = (const float*)d_in[3];
    const float* W2 = (const float*)d_in[4];
    const float* b2 = (const float*)d_in[5];
    float* out = (float*)d_out;

    int n = in_sizes[0] / IN_DIM;
    int E = in_sizes[1] / 2;
    const int* src = ei;
    const int* dst = ei + E;

    const int TB = 256;
    int gb_n = (n + TB - 1) / TB;
    int gb_e = (E + TB - 1) / TB;

    k_zero<<<gb_n, TB>>>(n);
    k_degree<<<gb_e, TB>>>(dst, E);
    k_prep<<<gb_n, TB>>>(x, n);
    k_edge_agg1<<<gb_e, TB>>>(src, dst, E);
    k_node<<<gb_n, TB>>>(x, W1, b1, W2, b2, out, n);
    k_edge_agg2<<<gb_e, TB>>>(src, dst, out, E);
    k_final<<<gb_n, TB>>>(out, b2, n);
}

// round 14
// speedup vs baseline: 1.1240x; 1.0215x over previous
#include <cuda_runtime.h>
#include <cuda_fp16.h>

// GCN 2-layer, minimal-traffic formulation:
//   yh[i]  = fp16(x[i] * dinv[i])  (5 halves packed in 16B = ONE LDG.128)
//   z[d]   = sum_edges yh[src]     (fp32 red.v4 + red.f32 -> exact accumulation)
//   zt     = z*dinv + x*dinv^2 ; h = relu(zt@W1+b1) ; s = h.W2 ; t = s*dinv
//   out[d] = dinv[d]*(sum_edges t[src] + t[d]) + b2

#define MAXN 131072
#define IN_DIM 5
#define PAD 8
#define HID 128

__device__ float g_deg[MAXN];
__device__ float g_dinv[MAXN];
__device__ __align__(128) __half g_yh[MAXN * 8];   // 16B per node row
__device__ __align__(128) float g_z[MAXN * PAD];
__device__ float g_t[MAXN];

__device__ __forceinline__ void red_v4(float* p, float a, float b, float c, float d) {
    asm volatile("red.global.add.v4.f32 [%0], {%1, %2, %3, %4};"
                 :: "l"(p), "f"(a), "f"(b), "f"(c), "f"(d) : "memory");
}

__device__ __forceinline__ unsigned long long fma2(unsigned long long a,
                                                   unsigned long long b,
                                                   unsigned long long c) {
    unsigned long long d;
    asm("fma.rn.f32x2 %0, %1, %2, %3;" : "=l"(d) : "l"(a), "l"(b), "l"(c));
    return d;
}
__device__ __forceinline__ unsigned long long pack2(float lo, float hi) {
    unsigned long long d;
    asm("mov.b64 %0, {%1, %2};" : "=l"(d) : "f"(lo), "f"(hi));
    return d;
}
__device__ __forceinline__ void unpack2(unsigned long long v, float& lo, float& hi) {
    asm("mov.b64 {%0, %1}, %2;" : "=f"(lo), "=f"(hi) : "l"(v));
}

__global__ void k_zero(int n) {
    int i = blockIdx.x * blockDim.x + threadIdx.x;
    if (i >= n) return;
    g_deg[i] = 0.0f;
    float4 z4 = make_float4(0.f, 0.f, 0.f, 0.f);
    *(float4*)&g_z[i * PAD] = z4;
    *(float4*)&g_z[i * PAD + 4] = z4;
}

// ---- degree: 1 edge/thread (measured-fastest config) ----
__global__ void k_degree(const int* __restrict__ dst, int E) {
    int e = blockIdx.x * blockDim.x + threadIdx.x;
    if (e >= E) return;
    atomicAdd(&g_deg[dst[e]], 1.0f);
}

// ---- dinv + fp16-packed scaled features ----
__global__ void k_prep(const float* __restrict__ x, int n) {
    int i = blockIdx.x * blockDim.x + threadIdx.x;
    if (i >= n) return;
    float di = rsqrtf(g_deg[i] + 1.0f);
    g_dinv[i] = di;
    __half2 p0 = __floats2half2_rn(x[i * IN_DIM + 0] * di, x[i * IN_DIM + 1] * di);
    __half2 p1 = __floats2half2_rn(x[i * IN_DIM + 2] * di, x[i * IN_DIM + 3] * di);
    __half2 p2 = __floats2half2_rn(x[i * IN_DIM + 4] * di, 0.0f);
    uint4 v;
    v.x = *(unsigned int*)&p0;
    v.y = *(unsigned int*)&p1;
    v.z = *(unsigned int*)&p2;
    v.w = 0u;
    *(uint4*)&g_yh[i * 8] = v;
}

// ---- edge pass 1: z[dst] += y[src]; ONE LDG.128 gather + red.v4 + red.f32 ----
__global__ void k_edge_agg1(const int* __restrict__ src, const int* __restrict__ dst, int E) {
    int e = blockIdx.x * blockDim.x + threadIdx.x;
    if (e >= E) return;
    int s = src[e];
    int d = dst[e];
    uint4 v = *(const uint4*)&g_yh[s * 8];
    __half2 p0 = *(__half2*)&v.x;
    __half2 p1 = *(__half2*)&v.y;
    __half2 p2 = *(__half2*)&v.z;
    float2 f0 = __half22float2(p0);
    float2 f1 = __half22float2(p1);
    float2 f2 = __half22float2(p2);
    red_v4(&g_z[d * PAD], f0.x, f0.y, f1.x, f1.y);
    atomicAdd(&g_z[d * PAD + 4], f2.x);
}

// ---- per-node MLP: 1 thread/node, smem weights, f32x2 pair math ----
__global__ void k_node(const float* __restrict__ x,
                       const float* __restrict__ W1, const float* __restrict__ b1,
                       const float* __restrict__ W2, const float* __restrict__ b2,
                       float* __restrict__ out, int n) {
    __shared__ __align__(16) float sW1[IN_DIM * HID];
    __shared__ __align__(16) float sb1[HID];
    __shared__ __align__(16) float sW2[HID];
    for (int i = threadIdx.x; i < IN_DIM * HID; i += blockDim.x) sW1[i] = W1[i];
    if (threadIdx.x < HID) {
        sb1[threadIdx.x] = b1[threadIdx.x];
        sW2[threadIdx.x] = W2[threadIdx.x];
    }
    __syncthreads();

    int i = blockIdx.x * blockDim.x + threadIdx.x;
    if (i >= n) return;

    float di = g_dinv[i];
    float d2 = di * di;
    float4 z4 = *(const float4*)&g_z[i * PAD];
    float z5  = g_z[i * PAD + 4];
    float zt0 = z4.x * di + x[i * IN_DIM + 0] * d2;
    float zt1 = z4.y * di + x[i * IN_DIM + 1] * d2;
    float zt2 = z4.z * di + x[i * IN_DIM + 2] * d2;
    float zt3 = z4.w * di + x[i * IN_DIM + 3] * d2;
    float zt4 = z5  * di + x[i * IN_DIM + 4] * d2;

    unsigned long long zp0 = pack2(zt0, zt0);
    unsigned long long zp1 = pack2(zt1, zt1);
    unsigned long long zp2 = pack2(zt2, zt2);
    unsigned long long zp3 = pack2(zt3, zt3);
    unsigned long long zp4 = pack2(zt4, zt4);

    float s0 = 0.0f, s1 = 0.0f, s2 = 0.0f, s3 = 0.0f;
#pragma unroll
    for (int k = 0; k < HID; k += 4) {
        unsigned long long a = *(const unsigned long long*)&sb1[k];
        a = fma2(zp0, *(const unsigned long long*)&sW1[0 * HID + k], a);
        a = fma2(zp1, *(const unsigned long long*)&sW1[1 * HID + k], a);
        a = fma2(zp2, *(const unsigned long long*)&sW1[2 * HID + k], a);
        a = fma2(zp3, *(const unsigned long long*)&sW1[3 * HID + k], a);
        a = fma2(zp4, *(const unsigned long long*)&sW1[4 * HID + k], a);
        unsigned long long b = *(const unsigned long long*)&sb1[k + 2];
        b = fma2(zp0, *(const unsigned long long*)&sW1[0 * HID + k + 2], b);
        b = fma2(zp1, *(const unsigned long long*)&sW1[1 * HID + k + 2], b);
        b = fma2(zp2, *(const unsigned long long*)&sW1[2 * HID + k + 2], b);
        b = fma2(zp3, *(const unsigned long long*)&sW1[3 * HID + k + 2], b);
        b = fma2(zp4, *(const unsigned long long*)&sW1[4 * HID + k + 2], b);
        float a0, a1, b0, b1v;
        unpack2(a, a0, a1);
        unpack2(b, b0, b1v);
        float w2a0, w2a1, w2b0, w2b1;
        unpack2(*(const unsigned long long*)&sW2[k], w2a0, w2a1);
        unpack2(*(const unsigned long long*)&sW2[k + 2], w2b0, w2b1);
        s0 = fmaf(fmaxf(a0, 0.0f), w2a0, s0);
        s1 = fmaf(fmaxf(a1, 0.0f), w2a1, s1);
        s2 = fmaf(fmaxf(b0, 0.0f), w2b0, s2);
        s3 = fmaf(fmaxf(b1v, 0.0f), w2b1, s3);
    }
    float s = (s0 + s1) + (s2 + s3);
    float t = s * di;
    g_t[i] = t;
    out[i] = t;              // self-loop term, pre-scale; k_final applies *dinv + b2
}

// ---- edge pass 2: out[dst] += t[src] (reads only g_t -> no race) ----
__global__ void k_edge_agg2(const int* __restrict__ src, const int* __restrict__ dst,
                            float* __restrict__ out, int E) {
    int e = blockIdx.x * blockDim.x + threadIdx.x;
    if (e >= E) return;
    atomicAdd(&out[dst[e]], g_t[src[e]]);
}

__global__ void k_final(float* __restrict__ out, const float* __restrict__ b2, int n) {
    int i = blockIdx.x * blockDim.x + threadIdx.x;
    if (i >= n) return;
    out[i] = out[i] * g_dinv[i] + __ldg(&b2[0]);
}

extern "C" void kernel_launch(void* const* d_in, const int* in_sizes, int n_in,
                              void* d_out, int out_size) {
    const float* x  = (const float*)d_in[0];
    const int* ei   = (const int*)d_in[1];   // [2, E]: src row then dst row
    const float* W1 = (const float*)d_in[2];
    const float* b1 = (const float*)d_in[3];
    const float* W2 = (const float*)d_in[4];
    const float* b2 = (const float*)d_in[5];
    float* out = (float*)d_out;

    int n = in_sizes[0] / IN_DIM;
    int E = in_sizes[1] / 2;
    const int* src = ei;
    const int* dst = ei + E;

    const int TB = 256;
    int gb_n = (n + TB - 1) / TB;
    int gb_e = (E + TB - 1) / TB;

    k_zero<<<gb_n, TB>>>(n);
    k_degree<<<gb_e, TB>>>(dst, E);
    k_prep<<<gb_n, TB>>>(x, n);
    k_edge_agg1<<<gb_e, TB>>>(src, dst, E);
    k_node<<<gb_n, TB>>>(x, W1, b1, W2, b2, out, n);
    k_edge_agg2<<<gb_e, TB>>>(src, dst, out, E);
    k_final<<<gb_n, TB>>>(out, b2, n);
}

// round 15
// speedup vs baseline: 1.2531x; 1.1148x over previous
#include <cuda_runtime.h>
#include <cuda_fp16.h>

// GCN 2-layer, minimal-traffic formulation:
//   yh[i]  = fp16(x[i] * dinv[i])   (5 halves packed in 16B = ONE LDG.128)
//   zh[d]  = sum_edges yh[src]      (ONE red.v4.f16x2 per edge = 8 halves)
//   zt     = zh*dinv + x*dinv^2 ; h = relu(zt@W1+b1) ; s = h.W2 ; t = s*dinv
//   out[d] = dinv[d]*(sum_edges t[src] + t[d]) + b2

#define MAXN 131072
#define IN_DIM 5
#define HID 128

__device__ float g_deg[MAXN];
__device__ float g_dinv[MAXN];
__device__ __align__(128) __half g_yh[MAXN * 8];   // 16B per node row
__device__ __align__(128) __half g_zh[MAXN * 8];   // fp16 accumulator, 16B per node
__device__ float g_t[MAXN];

// one 16B fp16 reduction: 8 halves as 4x f16x2
__device__ __forceinline__ void red_v4_f16x2(__half* p, unsigned int a, unsigned int b,
                                             unsigned int c, unsigned int d) {
    asm volatile("red.global.add.noftz.v4.f16x2 [%0], {%1, %2, %3, %4};"
                 :: "l"(p), "r"(a), "r"(b), "r"(c), "r"(d) : "memory");
}

__device__ __forceinline__ unsigned long long fma2(unsigned long long a,
                                                   unsigned long long b,
                                                   unsigned long long c) {
    unsigned long long d;
    asm("fma.rn.f32x2 %0, %1, %2, %3;" : "=l"(d) : "l"(a), "l"(b), "l"(c));
    return d;
}
__device__ __forceinline__ unsigned long long pack2(float lo, float hi) {
    unsigned long long d;
    asm("mov.b64 %0, {%1, %2};" : "=l"(d) : "f"(lo), "f"(hi));
    return d;
}
__device__ __forceinline__ void unpack2(unsigned long long v, float& lo, float& hi) {
    asm("mov.b64 {%0, %1}, %2;" : "=f"(lo), "=f"(hi) : "l"(v));
}

// ---- zero only the degree array (z is zeroed inside k_prep) ----
__global__ void k_zero(int n) {
    int i = blockIdx.x * blockDim.x + threadIdx.x;
    if (i >= n) return;
    g_deg[i] = 0.0f;
}

// ---- degree: 1 edge/thread (measured-fastest config) ----
__global__ void k_degree(const int* __restrict__ dst, int E) {
    int e = blockIdx.x * blockDim.x + threadIdx.x;
    if (e >= E) return;
    atomicAdd(&g_deg[dst[e]], 1.0f);
}

// ---- dinv + fp16-packed scaled features + zero the z accumulator ----
__global__ void k_prep(const float* __restrict__ x, int n) {
    int i = blockIdx.x * blockDim.x + threadIdx.x;
    if (i >= n) return;
    float di = rsqrtf(g_deg[i] + 1.0f);
    g_dinv[i] = di;
    __half2 p0 = __floats2half2_rn(x[i * IN_DIM + 0] * di, x[i * IN_DIM + 1] * di);
    __half2 p1 = __floats2half2_rn(x[i * IN_DIM + 2] * di, x[i * IN_DIM + 3] * di);
    __half2 p2 = __floats2half2_rn(x[i * IN_DIM + 4] * di, 0.0f);
    uint4 v;
    v.x = *(unsigned int*)&p0;
    v.y = *(unsigned int*)&p1;
    v.z = *(unsigned int*)&p2;
    v.w = 0u;
    *(uint4*)&g_yh[i * 8] = v;
    *(uint4*)&g_zh[i * 8] = make_uint4(0u, 0u, 0u, 0u);   // zh := 0
}

// ---- edge pass 1: zh[dst] += yh[src]; ONE LDG.128 + ONE red.v4.f16x2 ----
__global__ void k_edge_agg1(const int* __restrict__ src, const int* __restrict__ dst, int E) {
    int e = blockIdx.x * blockDim.x + threadIdx.x;
    if (e >= E) return;
    int s = src[e];
    int d = dst[e];
    uint4 v = *(const uint4*)&g_yh[s * 8];
    red_v4_f16x2(&g_zh[d * 8], v.x, v.y, v.z, v.w);   // lanes 5..7 add zero
}

// ---- per-node MLP: 1 thread/node, smem weights, f32x2 pair math ----
__global__ void k_node(const float* __restrict__ x,
                       const float* __restrict__ W1, const float* __restrict__ b1,
                       const float* __restrict__ W2, const float* __restrict__ b2,
                       float* __restrict__ out, int n) {
    __shared__ __align__(16) float sW1[IN_DIM * HID];
    __shared__ __align__(16) float sb1[HID];
    __shared__ __align__(16) float sW2[HID];
    for (int i = threadIdx.x; i < IN_DIM * HID; i += blockDim.x) sW1[i] = W1[i];
    if (threadIdx.x < HID) {
        sb1[threadIdx.x] = b1[threadIdx.x];
        sW2[threadIdx.x] = W2[threadIdx.x];
    }
    __syncthreads();

    int i = blockIdx.x * blockDim.x + threadIdx.x;
    if (i >= n) return;

    float di = g_dinv[i];
    float d2 = di * di;
    uint4 zv = *(const uint4*)&g_zh[i * 8];
    float2 f0 = __half22float2(*(__half2*)&zv.x);
    float2 f1 = __half22float2(*(__half2*)&zv.y);
    float2 f2 = __half22float2(*(__half2*)&zv.z);
    float zt0 = f0.x * di + x[i * IN_DIM + 0] * d2;
    float zt1 = f0.y * di + x[i * IN_DIM + 1] * d2;
    float zt2 = f1.x * di + x[i * IN_DIM + 2] * d2;
    float zt3 = f1.y * di + x[i * IN_DIM + 3] * d2;
    float zt4 = f2.x * di + x[i * IN_DIM + 4] * d2;

    unsigned long long zp0 = pack2(zt0, zt0);
    unsigned long long zp1 = pack2(zt1, zt1);
    unsigned long long zp2 = pack2(zt2, zt2);
    unsigned long long zp3 = pack2(zt3, zt3);
    unsigned long long zp4 = pack2(zt4, zt4);

    float s0 = 0.0f, s1 = 0.0f, s2 = 0.0f, s3 = 0.0f;
#pragma unroll
    for (int k = 0; k < HID; k += 4) {
        unsigned long long a = *(const unsigned long long*)&sb1[k];
        a = fma2(zp0, *(const unsigned long long*)&sW1[0 * HID + k], a);
        a = fma2(zp1, *(const unsigned long long*)&sW1[1 * HID + k], a);
        a = fma2(zp2, *(const unsigned long long*)&sW1[2 * HID + k], a);
        a = fma2(zp3, *(const unsigned long long*)&sW1[3 * HID + k], a);
        a = fma2(zp4, *(const unsigned long long*)&sW1[4 * HID + k], a);
        unsigned long long b = *(const unsigned long long*)&sb1[k + 2];
        b = fma2(zp0, *(const unsigned long long*)&sW1[0 * HID + k + 2], b);
        b = fma2(zp1, *(const unsigned long long*)&sW1[1 * HID + k + 2], b);
        b = fma2(zp2, *(const unsigned long long*)&sW1[2 * HID + k + 2], b);
        b = fma2(zp3, *(const unsigned long long*)&sW1[3 * HID + k + 2], b);
        b = fma2(zp4, *(const unsigned long long*)&sW1[4 * HID + k + 2], b);
        float a0, a1, b0, b1v;
        unpack2(a, a0, a1);
        unpack2(b, b0, b1v);
        float w2a0, w2a1, w2b0, w2b1;
        unpack2(*(const unsigned long long*)&sW2[k], w2a0, w2a1);
        unpack2(*(const unsigned long long*)&sW2[k + 2], w2b0, w2b1);
        s0 = fmaf(fmaxf(a0, 0.0f), w2a0, s0);
        s1 = fmaf(fmaxf(a1, 0.0f), w2a1, s1);
        s2 = fmaf(fmaxf(b0, 0.0f), w2b0, s2);
        s3 = fmaf(fmaxf(b1v, 0.0f), w2b1, s3);
    }
    float s = (s0 + s1) + (s2 + s3);
    float t = s * di;
    g_t[i] = t;
    out[i] = t;              // self-loop term, pre-scale; k_final applies *dinv + b2
}

// ---- edge pass 2: out[dst] += t[src] (reads only g_t -> no race) ----
__global__ void k_edge_agg2(const int* __restrict__ src, const int* __restrict__ dst,
                            float* __restrict__ out, int E) {
    int e = blockIdx.x * blockDim.x + threadIdx.x;
    if (e >= E) return;
    atomicAdd(&out[dst[e]], g_t[src[e]]);
}

__global__ void k_final(float* __restrict__ out, const float* __restrict__ b2, int n) {
    int i = blockIdx.x * blockDim.x + threadIdx.x;
    if (i >= n) return;
    out[i] = out[i] * g_dinv[i] + __ldg(&b2[0]);
}

extern "C" void kernel_launch(void* const* d_in, const int* in_sizes, int n_in,
                              void* d_out, int out_size) {
    const float* x  = (const float*)d_in[0];
    const int* ei   = (const int*)d_in[1];   // [2, E]: src row then dst row
    const float* W1 = (const float*)d_in[2];
    const float* b1 = (const float*)d_in[3];
    const float* W2 = (const float*)d_in[4];
    const float* b2 = (const float*)d_in[5];
    float* out = (float*)d_out;

    int n = in_sizes[0] / IN_DIM;
    int E = in_sizes[1] / 2;
    const int* src = ei;
    const int* dst = ei + E;

    const int TB = 256;
    int gb_n = (n + TB - 1) / TB;
    int gb_e = (E + TB - 1) / TB;

    k_zero<<<gb_n, TB>>>(n);
    k_degree<<<gb_e, TB>>>(dst, E);
    k_prep<<<gb_n, TB>>>(x, n);
    k_edge_agg1<<<gb_e, TB>>>(src, dst, E);
    k_node<<<gb_n, TB>>>(x, W1, b1, W2, b2, out, n);
    k_edge_agg2<<<gb_e, TB>>>(src, dst, out, E);
    k_final<<<gb_n, TB>>>(out, b2, n);
}

// round 16
// speedup vs baseline: 1.2949x; 1.0334x over previous
#include <cuda_runtime.h>
#include <cuda_fp16.h>

// GCN 2-layer, minimal-traffic formulation:
//   yh[i]  = fp16(x[i] * dinv[i])   (5 halves packed in 16B = ONE LDG.128)
//   zh[d]  = sum_edges yh[src]      (ONE red.v4.f16x2 per edge = 8 halves)
//   zt     = zh*dinv + x*dinv^2 ; h = relu(zt@W1+b1) ; s = h.W2 ; t = s*dinv
//   out[d] = dinv[d]*(sum_edges t[src] + t[d]) + b2
//
// g_deg is zeroed at the END of the graph (k_final); module-load zero-init
// covers the first call, so every invocation sees deg=0 at entry.

#define MAXN 131072
#define IN_DIM 5
#define HID 128

__device__ float g_deg[MAXN];
__device__ float g_dinv[MAXN];
__device__ __align__(128) __half g_yh[MAXN * 8];   // 16B per node row
__device__ __align__(128) __half g_zh[MAXN * 8];   // fp16 accumulator, 16B per node
__device__ float g_t[MAXN];

// one 16B fp16 reduction: 8 halves as 4x f16x2
__device__ __forceinline__ void red_v4_f16x2(__half* p, unsigned int a, unsigned int b,
                                             unsigned int c, unsigned int d) {
    asm volatile("red.global.add.noftz.v4.f16x2 [%0], {%1, %2, %3, %4};"
                 :: "l"(p), "r"(a), "r"(b), "r"(c), "r"(d) : "memory");
}

__device__ __forceinline__ unsigned long long fma2(unsigned long long a,
                                                   unsigned long long b,
                                                   unsigned long long c) {
    unsigned long long d;
    asm("fma.rn.f32x2 %0, %1, %2, %3;" : "=l"(d) : "l"(a), "l"(b), "l"(c));
    return d;
}
__device__ __forceinline__ unsigned long long pack2(float lo, float hi) {
    unsigned long long d;
    asm("mov.b64 %0, {%1, %2};" : "=l"(d) : "f"(lo), "f"(hi));
    return d;
}
__device__ __forceinline__ void unpack2(unsigned long long v, float& lo, float& hi) {
    asm("mov.b64 {%0, %1}, %2;" : "=f"(lo), "=f"(hi) : "l"(v));
}

// ---- degree: 1 edge/thread (measured-fastest config) ----
__global__ void k_degree(const int* __restrict__ dst, int E) {
    int e = blockIdx.x * blockDim.x + threadIdx.x;
    if (e >= E) return;
    atomicAdd(&g_deg[dst[e]], 1.0f);
}

// ---- dinv + fp16-packed scaled features + zero the z accumulator ----
__global__ void k_prep(const float* __restrict__ x, int n) {
    int i = blockIdx.x * blockDim.x + threadIdx.x;
    if (i >= n) return;
    float di = rsqrtf(g_deg[i] + 1.0f);
    g_dinv[i] = di;
    __half2 p0 = __floats2half2_rn(x[i * IN_DIM + 0] * di, x[i * IN_DIM + 1] * di);
    __half2 p1 = __floats2half2_rn(x[i * IN_DIM + 2] * di, x[i * IN_DIM + 3] * di);
    __half2 p2 = __floats2half2_rn(x[i * IN_DIM + 4] * di, 0.0f);
    uint4 v;
    v.x = *(unsigned int*)&p0;
    v.y = *(unsigned int*)&p1;
    v.z = *(unsigned int*)&p2;
    v.w = 0u;
    *(uint4*)&g_yh[i * 8] = v;
    *(uint4*)&g_zh[i * 8] = make_uint4(0u, 0u, 0u, 0u);   // zh := 0
}

// ---- edge pass 1: zh[dst] += yh[src]; ONE LDG.128 + ONE red.v4.f16x2 ----
__global__ void k_edge_agg1(const int* __restrict__ src, const int* __restrict__ dst, int E) {
    int e = blockIdx.x * blockDim.x + threadIdx.x;
    if (e >= E) return;
    int s = src[e];
    int d = dst[e];
    uint4 v = *(const uint4*)&g_yh[s * 8];
    red_v4_f16x2(&g_zh[d * 8], v.x, v.y, v.z, v.w);   // lanes 5..7 add zero
}

// ---- per-node MLP: 1 thread/node, smem weights, f32x2 pair math ----
__global__ void k_node(const float* __restrict__ x,
                       const float* __restrict__ W1, const float* __restrict__ b1,
                       const float* __restrict__ W2, const float* __restrict__ b2,
                       float* __restrict__ out, int n) {
    __shared__ __align__(16) float sW1[IN_DIM * HID];
    __shared__ __align__(16) float sb1[HID];
    __shared__ __align__(16) float sW2[HID];
    for (int i = threadIdx.x; i < IN_DIM * HID; i += blockDim.x) sW1[i] = W1[i];
    if (threadIdx.x < HID) {
        sb1[threadIdx.x] = b1[threadIdx.x];
        sW2[threadIdx.x] = W2[threadIdx.x];
    }
    __syncthreads();

    int i = blockIdx.x * blockDim.x + threadIdx.x;
    if (i >= n) return;

    float di = g_dinv[i];
    float d2 = di * di;
    uint4 zv = *(const uint4*)&g_zh[i * 8];
    float2 f0 = __half22float2(*(__half2*)&zv.x);
    float2 f1 = __half22float2(*(__half2*)&zv.y);
    float2 f2 = __half22float2(*(__half2*)&zv.z);
    float zt0 = f0.x * di + x[i * IN_DIM + 0] * d2;
    float zt1 = f0.y * di + x[i * IN_DIM + 1] * d2;
    float zt2 = f1.x * di + x[i * IN_DIM + 2] * d2;
    float zt3 = f1.y * di + x[i * IN_DIM + 3] * d2;
    float zt4 = f2.x * di + x[i * IN_DIM + 4] * d2;

    unsigned long long zp0 = pack2(zt0, zt0);
    unsigned long long zp1 = pack2(zt1, zt1);
    unsigned long long zp2 = pack2(zt2, zt2);
    unsigned long long zp3 = pack2(zt3, zt3);
    unsigned long long zp4 = pack2(zt4, zt4);

    float s0 = 0.0f, s1 = 0.0f, s2 = 0.0f, s3 = 0.0f;
#pragma unroll
    for (int k = 0; k < HID; k += 4) {
        unsigned long long a = *(const unsigned long long*)&sb1[k];
        a = fma2(zp0, *(const unsigned long long*)&sW1[0 * HID + k], a);
        a = fma2(zp1, *(const unsigned long long*)&sW1[1 * HID + k], a);
        a = fma2(zp2, *(const unsigned long long*)&sW1[2 * HID + k], a);
        a = fma2(zp3, *(const unsigned long long*)&sW1[3 * HID + k], a);
        a = fma2(zp4, *(const unsigned long long*)&sW1[4 * HID + k], a);
        unsigned long long b = *(const unsigned long long*)&sb1[k + 2];
        b = fma2(zp0, *(const unsigned long long*)&sW1[0 * HID + k + 2], b);
        b = fma2(zp1, *(const unsigned long long*)&sW1[1 * HID + k + 2], b);
        b = fma2(zp2, *(const unsigned long long*)&sW1[2 * HID + k + 2], b);
        b = fma2(zp3, *(const unsigned long long*)&sW1[3 * HID + k + 2], b);
        b = fma2(zp4, *(const unsigned long long*)&sW1[4 * HID + k + 2], b);
        float a0, a1, b0, b1v;
        unpack2(a, a0, a1);
        unpack2(b, b0, b1v);
        float w2a0, w2a1, w2b0, w2b1;
        unpack2(*(const unsigned long long*)&sW2[k], w2a0, w2a1);
        unpack2(*(const unsigned long long*)&sW2[k + 2], w2b0, w2b1);
        s0 = fmaf(fmaxf(a0, 0.0f), w2a0, s0);
        s1 = fmaf(fmaxf(a1, 0.0f), w2a1, s1);
        s2 = fmaf(fmaxf(b0, 0.0f), w2b0, s2);
        s3 = fmaf(fmaxf(b1v, 0.0f), w2b1, s3);
    }
    float s = (s0 + s1) + (s2 + s3);
    float t = s * di;
    g_t[i] = t;
    out[i] = t;              // self-loop term, pre-scale; k_final applies *dinv + b2
}

// ---- edge pass 2: out[dst] += t[src] (reads only g_t -> no race) ----
__global__ void k_edge_agg2(const int* __restrict__ src, const int* __restrict__ dst,
                            float* __restrict__ out, int E) {
    int e = blockIdx.x * blockDim.x + threadIdx.x;
    if (e >= E) return;
    atomicAdd(&out[dst[e]], g_t[src[e]]);
}

// ---- final scale + bias; also reset g_deg for the next invocation ----
__global__ void k_final(float* __restrict__ out, const float* __restrict__ b2, int n) {
    int i = blockIdx.x * blockDim.x + threadIdx.x;
    if (i >= n) return;
    out[i] = out[i] * g_dinv[i] + __ldg(&b2[0]);
    g_deg[i] = 0.0f;
}

extern "C" void kernel_launch(void* const* d_in, const int* in_sizes, int n_in,
                              void* d_out, int out_size) {
    const float* x  = (const float*)d_in[0];
    const int* ei   = (const int*)d_in[1];   // [2, E]: src row then dst row
    const float* W1 = (const float*)d_in[2];
    const float* b1 = (const float*)d_in[3];
    const float* W2 = (const float*)d_in[4];
    const float* b2 = (const float*)d_in[5];
    float* out = (float*)d_out;

    int n = in_sizes[0] / IN_DIM;
    int E = in_sizes[1] / 2;
    const int* src = ei;
    const int* dst = ei + E;

    const int TB = 256;
    int gb_n = (n + TB - 1) / TB;
    int gb_e = (E + TB - 1) / TB;

    k_degree<<<gb_e, TB>>>(dst, E);
    k_prep<<<gb_n, TB>>>(x, n);
    k_edge_agg1<<<gb_e, TB>>>(src, dst, E);
    k_node<<<gb_n, TB>>>(x, W1, b1, W2, b2, out, n);
    k_edge_agg2<<<gb_e, TB>>>(src, dst, out, E);
    k_final<<<gb_n, TB>>>(out, b2, n);
}

// round 17
// speedup vs baseline: 1.2994x; 1.0035x over previous
#include <cuda_runtime.h>
#include <cuda_fp16.h>

// GCN 2-layer, minimal-traffic formulation:
//   yh[i]  = fp16(x[i] * dinv[i])   (5 halves packed in 16B = ONE LDG.128)
//   zh[d]  = sum_edges yh[src]      (ONE red.v4.f16x2 per edge = 8 halves)
//   zt     = zh*dinv + x*dinv^2 ; h = relu(zt@W1+b1) ; s = h.W2 ; t = s*dinv
//   out[d] = dinv[d]*(sum_edges t[src] + t[d]) + b2
//
// g_deg is zeroed at the END of the graph (k_final); module-load zero-init
// covers the first call, so every invocation sees deg=0 at entry.

#define MAXN 131072
#define IN_DIM 5
#define HID 128

__device__ float g_deg[MAXN];
__device__ float g_dinv[MAXN];
__device__ __align__(128) __half g_yh[MAXN * 8];   // 16B per node row
__device__ __align__(128) __half g_zh[MAXN * 8];   // fp16 accumulator, 16B per node
__device__ float g_t[MAXN];

// one 16B fp16 reduction: 8 halves as 4x f16x2
__device__ __forceinline__ void red_v4_f16x2(__half* p, unsigned int a, unsigned int b,
                                             unsigned int c, unsigned int d) {
    asm volatile("red.global.add.noftz.v4.f16x2 [%0], {%1, %2, %3, %4};"
                 :: "l"(p), "r"(a), "r"(b), "r"(c), "r"(d) : "memory");
}

__device__ __forceinline__ unsigned long long fma2(unsigned long long a,
                                                   unsigned long long b,
                                                   unsigned long long c) {
    unsigned long long d;
    asm("fma.rn.f32x2 %0, %1, %2, %3;" : "=l"(d) : "l"(a), "l"(b), "l"(c));
    return d;
}
__device__ __forceinline__ unsigned long long pack2(float lo, float hi) {
    unsigned long long d;
    asm("mov.b64 %0, {%1, %2};" : "=l"(d) : "f"(lo), "f"(hi));
    return d;
}
__device__ __forceinline__ void unpack2(unsigned long long v, float& lo, float& hi) {
    asm("mov.b64 {%0, %1}, %2;" : "=f"(lo), "=f"(hi) : "l"(v));
}

// ---- degree: 1 edge/thread (measured-fastest config) ----
__global__ void k_degree(const int* __restrict__ dst, int E) {
    int e = blockIdx.x * blockDim.x + threadIdx.x;
    if (e >= E) return;
    atomicAdd(&g_deg[dst[e]], 1.0f);
}

// ---- dinv + fp16-packed scaled features + zero the z accumulator ----
__global__ void k_prep(const float* __restrict__ x, int n) {
    int i = blockIdx.x * blockDim.x + threadIdx.x;
    if (i >= n) return;
    float di = rsqrtf(g_deg[i] + 1.0f);
    g_dinv[i] = di;
    __half2 p0 = __floats2half2_rn(x[i * IN_DIM + 0] * di, x[i * IN_DIM + 1] * di);
    __half2 p1 = __floats2half2_rn(x[i * IN_DIM + 2] * di, x[i * IN_DIM + 3] * di);
    __half2 p2 = __floats2half2_rn(x[i * IN_DIM + 4] * di, 0.0f);
    uint4 v;
    v.x = *(unsigned int*)&p0;
    v.y = *(unsigned int*)&p1;
    v.z = *(unsigned int*)&p2;
    v.w = 0u;
    *(uint4*)&g_yh[i * 8] = v;
    *(uint4*)&g_zh[i * 8] = make_uint4(0u, 0u, 0u, 0u);   // zh := 0
}

// ---- edge pass 1: zh[dst] += yh[src]; ONE LDG.128 + ONE red.v4.f16x2 ----
__global__ void k_edge_agg1(const int* __restrict__ src, const int* __restrict__ dst, int E) {
    int e = blockIdx.x * blockDim.x + threadIdx.x;
    if (e >= E) return;
    int s = src[e];
    int d = dst[e];
    uint4 v = *(const uint4*)&g_yh[s * 8];
    red_v4_f16x2(&g_zh[d * 8], v.x, v.y, v.z, v.w);   // lanes 5..7 add zero
}

// ---- per-node MLP: 2 threads/node, f32x2 pairs, smem weights ----
// Thread kk in {0,1} handles unit-pairs k = 4q + 2kk (q = 0..31).
// Lane-pair LDS addresses differ by 8B -> conflict-free; broadcast across
// the 16 node-pairs per warp. Two independent accumulator chains per thread.
__global__ void k_node(const float* __restrict__ x,
                       const float* __restrict__ W1, const float* __restrict__ b1,
                       const float* __restrict__ W2, const float* __restrict__ b2,
                       float* __restrict__ out, int n) {
    __shared__ __align__(16) float sW1[IN_DIM * HID];
    __shared__ __align__(16) float sb1[HID];
    __shared__ __align__(16) float sW2[HID];
    for (int i = threadIdx.x; i < IN_DIM * HID; i += blockDim.x) sW1[i] = W1[i];
    if (threadIdx.x < HID) {
        sb1[threadIdx.x] = b1[threadIdx.x];
        sW2[threadIdx.x] = W2[threadIdx.x];
    }
    __syncthreads();

    int gt = blockIdx.x * blockDim.x + threadIdx.x;
    int i  = gt >> 1;          // node index
    int kk = gt & 1;           // pair-parity
    bool valid = (i < n);
    if (!valid) i = n - 1;     // clamp: keep lanes active for shfl

    float di = g_dinv[i];
    float d2 = di * di;
    uint4 zv = *(const uint4*)&g_zh[i * 8];
    float2 f0 = __half22float2(*(__half2*)&zv.x);
    float2 f1 = __half22float2(*(__half2*)&zv.y);
    float2 f2 = __half22float2(*(__half2*)&zv.z);
    float zt0 = f0.x * di + x[i * IN_DIM + 0] * d2;
    float zt1 = f0.y * di + x[i * IN_DIM + 1] * d2;
    float zt2 = f1.x * di + x[i * IN_DIM + 2] * d2;
    float zt3 = f1.y * di + x[i * IN_DIM + 3] * d2;
    float zt4 = f2.x * di + x[i * IN_DIM + 4] * d2;

    unsigned long long zp0 = pack2(zt0, zt0);
    unsigned long long zp1 = pack2(zt1, zt1);
    unsigned long long zp2 = pack2(zt2, zt2);
    unsigned long long zp3 = pack2(zt3, zt3);
    unsigned long long zp4 = pack2(zt4, zt4);

    int kbase = kk * 2;        // first pair index for this thread
    float s0 = 0.0f, s1 = 0.0f, s2 = 0.0f, s3 = 0.0f;
#pragma unroll
    for (int q = 0; q < HID / 8; q++) {
        // two pairs per iter for ILP: k = kbase + 8q and kbase + 8q + 4
        int ka = kbase + 8 * q;
        int kb = ka + 4;
        unsigned long long a = *(const unsigned long long*)&sb1[ka];
        a = fma2(zp0, *(const unsigned long long*)&sW1[0 * HID + ka], a);
        a = fma2(zp1, *(const unsigned long long*)&sW1[1 * HID + ka], a);
        a = fma2(zp2, *(const unsigned long long*)&sW1[2 * HID + ka], a);
        a = fma2(zp3, *(const unsigned long long*)&sW1[3 * HID + ka], a);
        a = fma2(zp4, *(const unsigned long long*)&sW1[4 * HID + ka], a);
        unsigned long long b = *(const unsigned long long*)&sb1[kb];
        b = fma2(zp0, *(const unsigned long long*)&sW1[0 * HID + kb], b);
        b = fma2(zp1, *(const unsigned long long*)&sW1[1 * HID + kb], b);
        b = fma2(zp2, *(const unsigned long long*)&sW1[2 * HID + kb], b);
        b = fma2(zp3, *(const unsigned long long*)&sW1[3 * HID + kb], b);
        b = fma2(zp4, *(const unsigned long long*)&sW1[4 * HID + kb], b);
        float a0, a1, b0, b1v;
        unpack2(a, a0, a1);
        unpack2(b, b0, b1v);
        float w2a0, w2a1, w2b0, w2b1;
        unpack2(*(const unsigned long long*)&sW2[ka], w2a0, w2a1);
        unpack2(*(const unsigned long long*)&sW2[kb], w2b0, w2b1);
        s0 = fmaf(fmaxf(a0, 0.0f), w2a0, s0);
        s1 = fmaf(fmaxf(a1, 0.0f), w2a1, s1);
        s2 = fmaf(fmaxf(b0, 0.0f), w2b0, s2);
        s3 = fmaf(fmaxf(b1v, 0.0f), w2b1, s3);
    }
    float s = (s0 + s1) + (s2 + s3);
    s += __shfl_xor_sync(0xFFFFFFFFu, s, 1);
    if (valid && kk == 0) {
        float t = s * di;
        g_t[i] = t;
        out[i] = t;          // self-loop term, pre-scale; k_final applies *dinv + b2
    }
}

// ---- edge pass 2: out[dst] += t[src] (reads only g_t -> no race) ----
__global__ void k_edge_agg2(const int* __restrict__ src, const int* __restrict__ dst,
                            float* __restrict__ out, int E) {
    int e = blockIdx.x * blockDim.x + threadIdx.x;
    if (e >= E) return;
    atomicAdd(&out[dst[e]], g_t[src[e]]);
}

// ---- final scale + bias; also reset g_deg for the next invocation ----
__global__ void k_final(float* __restrict__ out, const float* __restrict__ b2, int n) {
    int i = blockIdx.x * blockDim.x + threadIdx.x;
    if (i >= n) return;
    out[i] = out[i] * g_dinv[i] + __ldg(&b2[0]);
    g_deg[i] = 0.0f;
}

extern "C" void kernel_launch(void* const* d_in, const int* in_sizes, int n_in,
                              void* d_out, int out_size) {
    const float* x  = (const float*)d_in[0];
    const int* ei   = (const int*)d_in[1];   // [2, E]: src row then dst row
    const float* W1 = (const float*)d_in[2];
    const float* b1 = (const float*)d_in[3];
    const float* W2 = (const float*)d_in[4];
    const float* b2 = (const float*)d_in[5];
    float* out = (float*)d_out;

    int n = in_sizes[0] / IN_DIM;
    int E = in_sizes[1] / 2;
    const int* src = ei;
    const int* dst = ei + E;

    const int TB = 256;
    int gb_n  = (n + TB - 1) / TB;
    int gb_n2 = (n * 2 + TB - 1) / TB;
    int gb_e  = (E + TB - 1) / TB;

    k_degree<<<gb_e, TB>>>(dst, E);
    k_prep<<<gb_n, TB>>>(x, n);
    k_edge_agg1<<<gb_e, TB>>>(src, dst, E);
    k_node<<<gb_n2, TB>>>(x, W1, b1, W2, b2, out, n);
    k_edge_agg2<<<gb_e, TB>>>(src, dst, out, E);
    k_final<<<gb_n, TB>>>(out, b2, n);
}